// round 15
// baseline (speedup 1.0000x reference)
#include <cuda_runtime.h>
#include <cuda_bf16.h>
#include <cstdint>
#include <math.h>

#define BB 16
#define CC 256
#define NN 4096

// ---------------------------------------------------------------------------
// Device-global scratch (allocation-free per harness rules)
// ---------------------------------------------------------------------------
static __device__ __nv_bfloat16 g_s  [(size_t)BB * CC * NN];  // normalized sum
static __device__ __nv_bfloat16 g_x1b[(size_t)BB * CC * NN];  // bf16(x1) raw
static __device__ __nv_bfloat16 g_x2b[(size_t)BB * CC * NN];  // bf16(x2) raw
static __device__ __nv_bfloat16 g_x1t[(size_t)BB * CC * NN];  // bf16(x1) [b,n,d]
static __device__ __nv_bfloat16 g_x2t[(size_t)BB * CC * NN];
static __device__ float g_inv1[BB * CC];
static __device__ float g_inv2[BB * CC];
static __device__ __nv_bfloat16 g_ab1[(size_t)BB * CC * CC];  // softmaxed, bf16
static __device__ __nv_bfloat16 g_ab2[(size_t)BB * CC * CC];

// ---------------------------------------------------------------------------
// PTX helpers (base PTX only: cp.async / ldmatrix / mma.sync)
// ---------------------------------------------------------------------------
__device__ __forceinline__ uint32_t smem_to_u32(const void* p) {
    uint32_t a;
    asm("{ .reg .u64 t; cvta.to.shared.u64 t, %1; cvt.u32.u64 %0, t; }"
        : "=r"(a) : "l"(p));
    return a;
}

__device__ __forceinline__ void cp16(uint32_t dst, const void* src) {
    asm volatile("cp.async.cg.shared.global [%0], [%1], 16;\n"
                 :: "r"(dst), "l"(src));
}
__device__ __forceinline__ void cp_commit() {
    asm volatile("cp.async.commit_group;" ::: "memory");
}
template <int N>
__device__ __forceinline__ void cp_wait() {
    asm volatile("cp.async.wait_group %0;" :: "n"(N) : "memory");
}

__device__ __forceinline__ void ldsm4(uint32_t* r, uint32_t addr) {
    asm volatile("ldmatrix.sync.aligned.m8n8.x4.shared.b16 {%0,%1,%2,%3}, [%4];"
                 : "=r"(r[0]), "=r"(r[1]), "=r"(r[2]), "=r"(r[3])
                 : "r"(addr));
}

__device__ __forceinline__ void mma16816(float* c, const uint32_t* a,
                                         uint32_t b0, uint32_t b1) {
    asm volatile(
        "mma.sync.aligned.m16n8k16.row.col.f32.bf16.bf16.f32 "
        "{%0,%1,%2,%3}, {%4,%5,%6,%7}, {%8,%9}, {%0,%1,%2,%3};"
        : "+f"(c[0]), "+f"(c[1]), "+f"(c[2]), "+f"(c[3])
        : "r"(a[0]), "r"(a[1]), "r"(a[2]), "r"(a[3]), "r"(b0), "r"(b1));
}

__device__ __forceinline__ uint32_t pack2bf(float x, float y) {
    __nv_bfloat162 h = __floats2bfloat162_rn(x, y);
    return *reinterpret_cast<uint32_t*>(&h);
}
__device__ __forceinline__ uint2 pack4bf(float a, float b, float c, float d) {
    return make_uint2(pack2bf(a, b), pack2bf(c, d));
}

// ---------------------------------------------------------------------------
// Kernel 1: fused norm + bf16 conversion.  One block per (b,c) row.
//   g_s = bf16(x1*inv1 + x2*inv2); g_x1b/g_x2b = bf16 raw copies; invs saved.
// ---------------------------------------------------------------------------
__global__ void __launch_bounds__(256) fuse_k(const float* __restrict__ x1,
                                              const float* __restrict__ x2) {
    const int row = blockIdx.x;
    const size_t base4 = (size_t)row * (NN / 4);
    const float4* p1 = ((const float4*)x1) + base4;
    const float4* p2 = ((const float4*)x2) + base4;

    float4 a[4], c[4];
    float s1 = 0.f, s2 = 0.f;
    #pragma unroll
    for (int i = 0; i < 4; ++i) {
        a[i] = p1[threadIdx.x + i * 256];
        c[i] = p2[threadIdx.x + i * 256];
        s1 += a[i].x * a[i].x + a[i].y * a[i].y + a[i].z * a[i].z + a[i].w * a[i].w;
        s2 += c[i].x * c[i].x + c[i].y * c[i].y + c[i].z * c[i].z + c[i].w * c[i].w;
    }
    __shared__ float sh1[8], sh2[8];
    __shared__ float b_i1, b_i2;
    const int lane = threadIdx.x & 31, w = threadIdx.x >> 5;
    #pragma unroll
    for (int o = 16; o; o >>= 1) {
        s1 += __shfl_xor_sync(0xffffffffu, s1, o);
        s2 += __shfl_xor_sync(0xffffffffu, s2, o);
    }
    if (lane == 0) { sh1[w] = s1; sh2[w] = s2; }
    __syncthreads();
    if (threadIdx.x < 32) {
        s1 = (lane < 8) ? sh1[lane] : 0.f;
        s2 = (lane < 8) ? sh2[lane] : 0.f;
        #pragma unroll
        for (int o = 4; o; o >>= 1) {
            s1 += __shfl_xor_sync(0xffffffffu, s1, o);
            s2 += __shfl_xor_sync(0xffffffffu, s2, o);
        }
        if (lane == 0) {
            b_i1 = 1.f / fmaxf(sqrtf(s1), 1e-12f);
            b_i2 = 1.f / fmaxf(sqrtf(s2), 1e-12f);
            g_inv1[row] = b_i1;
            g_inv2[row] = b_i2;
        }
    }
    __syncthreads();
    const float i1 = b_i1, i2 = b_i2;

    uint2* os  = reinterpret_cast<uint2*>(g_s)   + base4;
    uint2* o1b = reinterpret_cast<uint2*>(g_x1b) + base4;
    uint2* o2b = reinterpret_cast<uint2*>(g_x2b) + base4;
    #pragma unroll
    for (int i = 0; i < 4; ++i) {
        const int idx = threadIdx.x + i * 256;
        o1b[idx] = pack4bf(a[i].x, a[i].y, a[i].z, a[i].w);
        o2b[idx] = pack4bf(c[i].x, c[i].y, c[i].z, c[i].w);
        os [idx] = pack4bf(a[i].x * i1 + c[i].x * i2, a[i].y * i1 + c[i].y * i2,
                           a[i].z * i1 + c[i].z * i2, a[i].w * i1 + c[i].w * i2);
    }
}

// ---------------------------------------------------------------------------
// Kernel 2: transpose bf16 -> bf16 [b, n, d] (reads g_x1b/g_x2b, bit-identical)
// ---------------------------------------------------------------------------
__global__ void __launch_bounds__(256) transpose_k() {
    __shared__ uint16_t t1[32][34], t2[32][34];
    const int b  = blockIdx.z;
    const int c0 = blockIdx.y * 32;
    const int n0 = blockIdx.x * 32;
    const int tx = threadIdx.x, ty = threadIdx.y;   // 32 x 8

    const uint16_t* s1 = (const uint16_t*)g_x1b;
    const uint16_t* s2 = (const uint16_t*)g_x2b;
    #pragma unroll
    for (int i = 0; i < 4; ++i) {
        const int r = ty + i * 8;
        const size_t idx = ((size_t)(b * CC + c0 + r)) * NN + n0 + tx;
        t1[r][tx] = s1[idx];
        t2[r][tx] = s2[idx];
    }
    __syncthreads();
    uint16_t* d1 = (uint16_t*)g_x1t;
    uint16_t* d2 = (uint16_t*)g_x2t;
    #pragma unroll
    for (int i = 0; i < 4; ++i) {
        const int r = ty + i * 8;
        const size_t o = ((size_t)b * NN + n0 + r) * CC + c0 + tx;
        d1[o] = t1[tx][r];
        d2[o] = t2[tx][r];
    }
}

// ---------------------------------------------------------------------------
// Kernel 3: score GEMM + fused softmax (round-7 proven shape, m-tile 64).
// ---------------------------------------------------------------------------
#define SC_BUF    40960                 // A (64x64x2=8KB) + B (256x64x2=32KB)
#define SC_SP     268                   // stash row stride (floats)
#define SC_SMEM   (2 * SC_BUF)          // 81920 >= 64*SC_SP*4 = 68608

__global__ void __launch_bounds__(256, 2) score_mma() {
    extern __shared__ char smem[];
    const uint32_t sb = smem_to_u32(smem);
    const int tid = threadIdx.x, lane = tid & 31, wid = tid >> 5;
    const int b   = blockIdx.y;
    const int sel = blockIdx.x >> 2;
    const int m0  = (blockIdx.x & 3) * 64;

    const __nv_bfloat16* bsrc = sel ? g_x2b : g_x1b;
    const float* ginv = (sel ? g_inv2 : g_inv1) + b * CC;
    __nv_bfloat16* gOut = (sel ? g_ab2 : g_ab1) + (size_t)b * CC * CC;
    const uint4* gA = (const uint4*)g_s  + (size_t)(b * CC + m0) * (NN / 8);
    const uint4* gB = (const uint4*)bsrc + (size_t)(b * CC) * (NN / 8);

    const int mW = (wid >> 2) * 32;               // warp m offset (0/32)
    const int nW = (wid & 3) * 64;                // warp d offset (0..192)
    const int lrow = lane & 15;
    const int lhi  = lane >> 4;

    float acc[2][8][4] = {};

    auto prefetch = [&](int ch, int buf) {
        const uint32_t aB = sb + buf * SC_BUF;
        const uint32_t bB = aB + 8192;
        #pragma unroll
        for (int i = 0; i < 2; ++i) {
            const int lin = i * 256 + tid;
            const int r = lin >> 3, c = lin & 7;
            cp16(aB + r * 128 + ((c ^ (r & 7)) << 4),
                 gA + (size_t)r * (NN / 8) + ch * 8 + c);
        }
        #pragma unroll
        for (int i = 0; i < 8; ++i) {
            const int lin = i * 256 + tid;
            const int r = lin >> 3, c = lin & 7;
            cp16(bB + r * 128 + ((c ^ (r & 7)) << 4),
                 gB + (size_t)r * (NN / 8) + ch * 8 + c);
        }
        cp_commit();
    };

    prefetch(0, 0);
    for (int ch = 0; ch < NN / 64; ++ch) {
        const int buf = ch & 1;
        if (ch + 1 < NN / 64) { prefetch(ch + 1, buf ^ 1); cp_wait<1>(); }
        else                  { cp_wait<0>(); }
        __syncthreads();

        const uint32_t aB = sb + buf * SC_BUF;
        const uint32_t bB = aB + 8192;
        #pragma unroll
        for (int ks = 0; ks < 4; ++ks) {
            uint32_t afr[2][4], bfr[4][4];
            #pragma unroll
            for (int mi = 0; mi < 2; ++mi) {
                const int r = mW + 16 * mi + lrow;
                ldsm4(afr[mi], aB + r * 128 + ((((ks << 1) | lhi) ^ (r & 7)) << 4));
            }
            #pragma unroll
            for (int nj = 0; nj < 4; ++nj) {
                const int r = nW + 16 * nj + lrow;
                ldsm4(bfr[nj], bB + r * 128 + ((((ks << 1) | lhi) ^ (r & 7)) << 4));
            }
            #pragma unroll
            for (int mi = 0; mi < 2; ++mi)
                #pragma unroll
                for (int ni = 0; ni < 8; ++ni)
                    mma16816(acc[mi][ni], afr[mi],
                             bfr[ni >> 1][ni & 1], bfr[ni >> 1][(ni & 1) + 2]);
        }
        __syncthreads();
    }

    // Stash aliases the (now dead) tile buffers; last loop sync protects it.
    float* stash = (float*)smem;
    float invv[8];
    #pragma unroll
    for (int j = 0; j < 8; ++j) invv[j] = ginv[lane + 32 * j];

    #pragma unroll
    for (int mi = 0; mi < 2; ++mi) {
        const int r = mW + 16 * mi + (lane >> 2);
        #pragma unroll
        for (int ni = 0; ni < 8; ++ni) {
            const int d = nW + 8 * ni + 2 * (lane & 3);
            *(float2*)&stash[(size_t)r * SC_SP + d] =
                make_float2(acc[mi][ni][0], acc[mi][ni][1]);
            *(float2*)&stash[(size_t)(r + 8) * SC_SP + d] =
                make_float2(acc[mi][ni][2], acc[mi][ni][3]);
        }
    }
    __syncthreads();

    #pragma unroll
    for (int i = 0; i < 8; ++i) {
        const int r = wid * 8 + i;
        const float* srow = stash + (size_t)r * SC_SP;
        float v[8];
        #pragma unroll
        for (int j = 0; j < 8; ++j) v[j] = srow[lane + 32 * j] * invv[j];
        float m = v[0];
        #pragma unroll
        for (int j = 1; j < 8; ++j) m = fmaxf(m, v[j]);
        #pragma unroll
        for (int o = 16; o; o >>= 1) m = fmaxf(m, __shfl_xor_sync(0xffffffffu, m, o));
        float e[8], s = 0.f;
        #pragma unroll
        for (int j = 0; j < 8; ++j) { e[j] = __expf(v[j] - m); s += e[j]; }
        #pragma unroll
        for (int o = 16; o; o >>= 1) s += __shfl_xor_sync(0xffffffffu, s, o);
        const float inv = 1.f / s;
        __nv_bfloat16* q = gOut + (size_t)(m0 + r) * CC;
        #pragma unroll
        for (int j = 0; j < 8; ++j)
            q[lane + 32 * j] = __float2bfloat16_rn(e[j] * inv);
    }
}

// ---------------------------------------------------------------------------
// Kernel 4: projection GEMM + residual, HIGH-ILP variant.
//   Per batch: D[4096, 256] = [x1t | x2t] (K=512) @ [ab1 | ab2]^T
//   out[b, n*256+c] = D[n,c] + x1[o] + x2[o]
//   CTA tile 128x128, 128 threads = 4 warps of 64x64 warp tiles:
//   8 ldsm per 32 MMAs (0.25 vs 0.375) to relieve the L1tex pipe (60.7%).
//   BK=64, 3-stage cp.async pipeline, ONE sync per chunk.
// ---------------------------------------------------------------------------
#define PJ_BUF  32768
#define PJ_SMEM (3 * PJ_BUF)            // 98304; 2 CTAs/SM = 192KB <= 228KB

__global__ void __launch_bounds__(128) proj_mma(const float* __restrict__ x1,
                                                const float* __restrict__ x2,
                                                float* __restrict__ out) {
    extern __shared__ char smem[];
    const uint32_t sb = smem_to_u32(smem);
    const int tid = threadIdx.x, lane = tid & 31, wid = tid >> 5;
    const int b  = blockIdx.z;
    const int n0 = blockIdx.y * 128;              // spatial (M)
    const int c0 = blockIdx.x * 128;              // channel (N)

    const uint4* gA1 = (const uint4*)g_x1t + ((size_t)b * NN + n0) * (CC / 8);
    const uint4* gA2 = (const uint4*)g_x2t + ((size_t)b * NN + n0) * (CC / 8);
    const uint4* gB1 = (const uint4*)g_ab1 + ((size_t)(b * CC + c0)) * (CC / 8);
    const uint4* gB2 = (const uint4*)g_ab2 + ((size_t)(b * CC + c0)) * (CC / 8);

    const int mW = (wid >> 1) * 64;               // warp n offset (0/64)
    const int nW = (wid & 1) * 64;                // warp c offset (0/64)
    const int lrow = lane & 15;
    const int lhi  = lane >> 4;

    float acc[4][8][4] = {};

    auto prefetch = [&](int ch, int buf) {
        const uint4* pa = (ch < 4) ? gA1 : gA2;
        const uint4* pb = (ch < 4) ? gB1 : gB2;
        const int kc = (ch & 3) * 8;              // uint4 offset within 256-half
        const uint32_t aB = sb + buf * PJ_BUF;
        const uint32_t bB = aB + 16384;
        #pragma unroll
        for (int i = 0; i < 8; ++i) {
            const int lin = i * 128 + tid;
            const int r = lin >> 3, c = lin & 7;
            const uint32_t off = r * 128 + ((c ^ (r & 7)) << 4);
            cp16(aB + off, pa + (size_t)r * (CC / 8) + kc + c);
            cp16(bB + off, pb + (size_t)r * (CC / 8) + kc + c);
        }
        cp_commit();
    };

    prefetch(0, 0);
    prefetch(1, 1);
    #pragma unroll 1
    for (int ch = 0; ch < 8; ++ch) {
        if (ch + 1 < 8) cp_wait<1>();             // oldest (ch) complete
        else            cp_wait<0>();
        __syncthreads();                          // all warps done with ch-1
        if (ch + 2 < 8) prefetch(ch + 2, (ch + 2) % 3);

        const uint32_t aB = sb + (ch % 3) * PJ_BUF;
        const uint32_t bB = aB + 16384;
        #pragma unroll
        for (int ks = 0; ks < 4; ++ks) {
            uint32_t afr[4][4], bfr[4][4];
            #pragma unroll
            for (int mi = 0; mi < 4; ++mi) {
                const int r = mW + 16 * mi + lrow;
                ldsm4(afr[mi], aB + r * 128 + ((((ks << 1) | lhi) ^ (r & 7)) << 4));
            }
            #pragma unroll
            for (int nj = 0; nj < 4; ++nj) {
                const int r = nW + 16 * nj + lrow;
                ldsm4(bfr[nj], bB + r * 128 + ((((ks << 1) | lhi) ^ (r & 7)) << 4));
            }
            #pragma unroll
            for (int mi = 0; mi < 4; ++mi)
                #pragma unroll
                for (int ni = 0; ni < 8; ++ni)
                    mma16816(acc[mi][ni], afr[mi],
                             bfr[ni >> 1][ni & 1], bfr[ni >> 1][(ni & 1) + 2]);
        }
    }

    // Epilogue: out[o] = acc + x1[o] + x2[o],  o = b*CC*NN + n*CC + c
    const size_t ob = (size_t)b * CC * NN;
    #pragma unroll
    for (int mi = 0; mi < 4; ++mi) {
        const int n = n0 + mW + 16 * mi + (lane >> 2);
        #pragma unroll
        for (int ni = 0; ni < 8; ++ni) {
            const int c = c0 + nW + 8 * ni + 2 * (lane & 3);
            {
                const size_t o = ob + (size_t)n * CC + c;
                float2 r1 = *(const float2*)(x1 + o);
                float2 r2 = *(const float2*)(x2 + o);
                *(float2*)(out + o) = make_float2(acc[mi][ni][0] + r1.x + r2.x,
                                                  acc[mi][ni][1] + r1.y + r2.y);
            }
            {
                const size_t o = ob + (size_t)(n + 8) * CC + c;
                float2 r1 = *(const float2*)(x1 + o);
                float2 r2 = *(const float2*)(x2 + o);
                *(float2*)(out + o) = make_float2(acc[mi][ni][2] + r1.x + r2.x,
                                                  acc[mi][ni][3] + r1.y + r2.y);
            }
        }
    }
}

// ---------------------------------------------------------------------------
extern "C" void kernel_launch(void* const* d_in, const int* in_sizes, int n_in,
                              void* d_out, int out_size) {
    const float* x1 = (const float*)d_in[0];
    const float* x2 = (const float*)d_in[1];
    float* out = (float*)d_out;

    cudaFuncSetAttribute(score_mma, cudaFuncAttributeMaxDynamicSharedMemorySize, SC_SMEM);
    cudaFuncSetAttribute(proj_mma,  cudaFuncAttributeMaxDynamicSharedMemorySize, PJ_SMEM);

    fuse_k     <<<BB * CC, 256>>>(x1, x2);
    transpose_k<<<dim3(NN / 32, CC / 32, BB), dim3(32, 8)>>>();
    score_mma  <<<dim3(8, BB), 256, SC_SMEM>>>();
    proj_mma   <<<dim3(2, 32, BB), 128, PJ_SMEM>>>(x1, x2, out);
}

// round 16
// speedup vs baseline: 1.0101x; 1.0101x over previous
#include <cuda_runtime.h>
#include <cuda_bf16.h>
#include <cstdint>
#include <math.h>

#define BB 16
#define CC 256
#define NN 4096

// ---------------------------------------------------------------------------
// Device-global scratch (allocation-free per harness rules)
// ---------------------------------------------------------------------------
static __device__ __nv_bfloat16 g_s  [(size_t)BB * CC * NN];  // normalized sum
static __device__ __nv_bfloat16 g_x1b[(size_t)BB * CC * NN];  // bf16(x1) raw
static __device__ __nv_bfloat16 g_x2b[(size_t)BB * CC * NN];  // bf16(x2) raw
static __device__ __nv_bfloat16 g_x1t[(size_t)BB * CC * NN];  // bf16(x1) [b,n,d]
static __device__ __nv_bfloat16 g_x2t[(size_t)BB * CC * NN];
static __device__ float g_inv1[BB * CC];
static __device__ float g_inv2[BB * CC];
static __device__ __nv_bfloat16 g_ab1[(size_t)BB * CC * CC];  // softmaxed, bf16
static __device__ __nv_bfloat16 g_ab2[(size_t)BB * CC * CC];

// ---------------------------------------------------------------------------
// PTX helpers (base PTX only: cp.async / ldmatrix / mma.sync)
// ---------------------------------------------------------------------------
__device__ __forceinline__ uint32_t smem_to_u32(const void* p) {
    uint32_t a;
    asm("{ .reg .u64 t; cvta.to.shared.u64 t, %1; cvt.u32.u64 %0, t; }"
        : "=r"(a) : "l"(p));
    return a;
}

__device__ __forceinline__ void cp16(uint32_t dst, const void* src) {
    asm volatile("cp.async.cg.shared.global [%0], [%1], 16;\n"
                 :: "r"(dst), "l"(src));
}
__device__ __forceinline__ void cp_commit() {
    asm volatile("cp.async.commit_group;" ::: "memory");
}
template <int N>
__device__ __forceinline__ void cp_wait() {
    asm volatile("cp.async.wait_group %0;" :: "n"(N) : "memory");
}

__device__ __forceinline__ void ldsm4(uint32_t* r, uint32_t addr) {
    asm volatile("ldmatrix.sync.aligned.m8n8.x4.shared.b16 {%0,%1,%2,%3}, [%4];"
                 : "=r"(r[0]), "=r"(r[1]), "=r"(r[2]), "=r"(r[3])
                 : "r"(addr));
}

__device__ __forceinline__ void mma16816(float* c, const uint32_t* a,
                                         uint32_t b0, uint32_t b1) {
    asm volatile(
        "mma.sync.aligned.m16n8k16.row.col.f32.bf16.bf16.f32 "
        "{%0,%1,%2,%3}, {%4,%5,%6,%7}, {%8,%9}, {%0,%1,%2,%3};"
        : "+f"(c[0]), "+f"(c[1]), "+f"(c[2]), "+f"(c[3])
        : "r"(a[0]), "r"(a[1]), "r"(a[2]), "r"(a[3]), "r"(b0), "r"(b1));
}

__device__ __forceinline__ uint32_t pack2bf(float x, float y) {
    __nv_bfloat162 h = __floats2bfloat162_rn(x, y);
    return *reinterpret_cast<uint32_t*>(&h);
}
__device__ __forceinline__ uint2 pack4bf(float a, float b, float c, float d) {
    return make_uint2(pack2bf(a, b), pack2bf(c, d));
}

// ---------------------------------------------------------------------------
// Kernel 1: fused norm + bf16 conversion.  One block per (b,c) row.
//   g_s = bf16(x1*inv1 + x2*inv2); g_x1b/g_x2b = bf16 raw copies; invs saved.
// ---------------------------------------------------------------------------
__global__ void __launch_bounds__(256) fuse_k(const float* __restrict__ x1,
                                              const float* __restrict__ x2) {
    const int row = blockIdx.x;
    const size_t base4 = (size_t)row * (NN / 4);
    const float4* p1 = ((const float4*)x1) + base4;
    const float4* p2 = ((const float4*)x2) + base4;

    float4 a[4], c[4];
    float s1 = 0.f, s2 = 0.f;
    #pragma unroll
    for (int i = 0; i < 4; ++i) {
        a[i] = p1[threadIdx.x + i * 256];
        c[i] = p2[threadIdx.x + i * 256];
        s1 += a[i].x * a[i].x + a[i].y * a[i].y + a[i].z * a[i].z + a[i].w * a[i].w;
        s2 += c[i].x * c[i].x + c[i].y * c[i].y + c[i].z * c[i].z + c[i].w * c[i].w;
    }
    __shared__ float sh1[8], sh2[8];
    __shared__ float b_i1, b_i2;
    const int lane = threadIdx.x & 31, w = threadIdx.x >> 5;
    #pragma unroll
    for (int o = 16; o; o >>= 1) {
        s1 += __shfl_xor_sync(0xffffffffu, s1, o);
        s2 += __shfl_xor_sync(0xffffffffu, s2, o);
    }
    if (lane == 0) { sh1[w] = s1; sh2[w] = s2; }
    __syncthreads();
    if (threadIdx.x < 32) {
        s1 = (lane < 8) ? sh1[lane] : 0.f;
        s2 = (lane < 8) ? sh2[lane] : 0.f;
        #pragma unroll
        for (int o = 4; o; o >>= 1) {
            s1 += __shfl_xor_sync(0xffffffffu, s1, o);
            s2 += __shfl_xor_sync(0xffffffffu, s2, o);
        }
        if (lane == 0) {
            b_i1 = 1.f / fmaxf(sqrtf(s1), 1e-12f);
            b_i2 = 1.f / fmaxf(sqrtf(s2), 1e-12f);
            g_inv1[row] = b_i1;
            g_inv2[row] = b_i2;
        }
    }
    __syncthreads();
    const float i1 = b_i1, i2 = b_i2;

    uint2* os  = reinterpret_cast<uint2*>(g_s)   + base4;
    uint2* o1b = reinterpret_cast<uint2*>(g_x1b) + base4;
    uint2* o2b = reinterpret_cast<uint2*>(g_x2b) + base4;
    #pragma unroll
    for (int i = 0; i < 4; ++i) {
        const int idx = threadIdx.x + i * 256;
        o1b[idx] = pack4bf(a[i].x, a[i].y, a[i].z, a[i].w);
        o2b[idx] = pack4bf(c[i].x, c[i].y, c[i].z, c[i].w);
        os [idx] = pack4bf(a[i].x * i1 + c[i].x * i2, a[i].y * i1 + c[i].y * i2,
                           a[i].z * i1 + c[i].z * i2, a[i].w * i1 + c[i].w * i2);
    }
}

// ---------------------------------------------------------------------------
// Kernel 2: transpose bf16 -> bf16 [b, n, d].  Reads the already-converted
// g_x1b/g_x2b (half the traffic of reading fp32 x1/x2; bit-identical output).
// uint16 smem [32][34]: column reads word-stride 17 (odd) -> conflict-free.
// ---------------------------------------------------------------------------
__global__ void __launch_bounds__(256) transpose_k() {
    __shared__ uint16_t t1[32][34], t2[32][34];
    const int b  = blockIdx.z;
    const int c0 = blockIdx.y * 32;
    const int n0 = blockIdx.x * 32;
    const int tx = threadIdx.x, ty = threadIdx.y;   // 32 x 8

    const uint16_t* s1 = (const uint16_t*)g_x1b;
    const uint16_t* s2 = (const uint16_t*)g_x2b;
    #pragma unroll
    for (int i = 0; i < 4; ++i) {
        const int r = ty + i * 8;
        const size_t idx = ((size_t)(b * CC + c0 + r)) * NN + n0 + tx;
        t1[r][tx] = s1[idx];
        t2[r][tx] = s2[idx];
    }
    __syncthreads();
    uint16_t* d1 = (uint16_t*)g_x1t;
    uint16_t* d2 = (uint16_t*)g_x2t;
    #pragma unroll
    for (int i = 0; i < 4; ++i) {
        const int r = ty + i * 8;
        const size_t o = ((size_t)b * NN + n0 + r) * CC + c0 + tx;
        d1[o] = t1[tx][r];
        d2[o] = t2[tx][r];
    }
}

// ---------------------------------------------------------------------------
// Kernel 3: score GEMM + fused softmax, mma.sync bf16 (round-7 proven shape).
//   scores[64, 256] = s[m0:m0+64, :] @ xRAW[0:256, :]^T, column-scale by
//   inv[d], row-softmax, bf16 out.  Stash aliases dead tile buffers.
// ---------------------------------------------------------------------------
#define SC_BUF    40960                 // A (64x64x2=8KB) + B (256x64x2=32KB)
#define SC_SP     268                   // stash row stride (floats)
#define SC_SMEM   (2 * SC_BUF)          // 81920 >= 64*SC_SP*4 = 68608

__global__ void __launch_bounds__(256, 2) score_mma() {
    extern __shared__ char smem[];
    const uint32_t sb = smem_to_u32(smem);
    const int tid = threadIdx.x, lane = tid & 31, wid = tid >> 5;
    const int b   = blockIdx.y;
    const int sel = blockIdx.x >> 2;
    const int m0  = (blockIdx.x & 3) * 64;

    const __nv_bfloat16* bsrc = sel ? g_x2b : g_x1b;
    const float* ginv = (sel ? g_inv2 : g_inv1) + b * CC;
    __nv_bfloat16* gOut = (sel ? g_ab2 : g_ab1) + (size_t)b * CC * CC;
    const uint4* gA = (const uint4*)g_s  + (size_t)(b * CC + m0) * (NN / 8);
    const uint4* gB = (const uint4*)bsrc + (size_t)(b * CC) * (NN / 8);

    const int mW = (wid >> 2) * 32;               // warp m offset (0/32)
    const int nW = (wid & 3) * 64;                // warp d offset (0..192)
    const int lrow = lane & 15;
    const int lhi  = lane >> 4;

    float acc[2][8][4] = {};

    auto prefetch = [&](int ch, int buf) {
        const uint32_t aB = sb + buf * SC_BUF;
        const uint32_t bB = aB + 8192;
        #pragma unroll
        for (int i = 0; i < 2; ++i) {
            const int lin = i * 256 + tid;
            const int r = lin >> 3, c = lin & 7;
            cp16(aB + r * 128 + ((c ^ (r & 7)) << 4),
                 gA + (size_t)r * (NN / 8) + ch * 8 + c);
        }
        #pragma unroll
        for (int i = 0; i < 8; ++i) {
            const int lin = i * 256 + tid;
            const int r = lin >> 3, c = lin & 7;
            cp16(bB + r * 128 + ((c ^ (r & 7)) << 4),
                 gB + (size_t)r * (NN / 8) + ch * 8 + c);
        }
        cp_commit();
    };

    prefetch(0, 0);
    for (int ch = 0; ch < NN / 64; ++ch) {
        const int buf = ch & 1;
        if (ch + 1 < NN / 64) { prefetch(ch + 1, buf ^ 1); cp_wait<1>(); }
        else                  { cp_wait<0>(); }
        __syncthreads();

        const uint32_t aB = sb + buf * SC_BUF;
        const uint32_t bB = aB + 8192;
        #pragma unroll
        for (int ks = 0; ks < 4; ++ks) {
            uint32_t afr[2][4], bfr[4][4];
            #pragma unroll
            for (int mi = 0; mi < 2; ++mi) {
                const int r = mW + 16 * mi + lrow;
                ldsm4(afr[mi], aB + r * 128 + ((((ks << 1) | lhi) ^ (r & 7)) << 4));
            }
            #pragma unroll
            for (int nj = 0; nj < 4; ++nj) {
                const int r = nW + 16 * nj + lrow;
                ldsm4(bfr[nj], bB + r * 128 + ((((ks << 1) | lhi) ^ (r & 7)) << 4));
            }
            #pragma unroll
            for (int mi = 0; mi < 2; ++mi)
                #pragma unroll
                for (int ni = 0; ni < 8; ++ni)
                    mma16816(acc[mi][ni], afr[mi],
                             bfr[ni >> 1][ni & 1], bfr[ni >> 1][(ni & 1) + 2]);
        }
        __syncthreads();
    }

    // Stash aliases the (now dead) tile buffers; last loop sync protects it.
    float* stash = (float*)smem;
    float invv[8];
    #pragma unroll
    for (int j = 0; j < 8; ++j) invv[j] = ginv[lane + 32 * j];

    #pragma unroll
    for (int mi = 0; mi < 2; ++mi) {
        const int r = mW + 16 * mi + (lane >> 2);
        #pragma unroll
        for (int ni = 0; ni < 8; ++ni) {
            const int d = nW + 8 * ni + 2 * (lane & 3);
            *(float2*)&stash[(size_t)r * SC_SP + d] =
                make_float2(acc[mi][ni][0], acc[mi][ni][1]);
            *(float2*)&stash[(size_t)(r + 8) * SC_SP + d] =
                make_float2(acc[mi][ni][2], acc[mi][ni][3]);
        }
    }
    __syncthreads();

    #pragma unroll
    for (int i = 0; i < 8; ++i) {
        const int r = wid * 8 + i;
        const float* srow = stash + (size_t)r * SC_SP;
        float v[8];
        #pragma unroll
        for (int j = 0; j < 8; ++j) v[j] = srow[lane + 32 * j] * invv[j];
        float m = v[0];
        #pragma unroll
        for (int j = 1; j < 8; ++j) m = fmaxf(m, v[j]);
        #pragma unroll
        for (int o = 16; o; o >>= 1) m = fmaxf(m, __shfl_xor_sync(0xffffffffu, m, o));
        float e[8], s = 0.f;
        #pragma unroll
        for (int j = 0; j < 8; ++j) { e[j] = __expf(v[j] - m); s += e[j]; }
        #pragma unroll
        for (int o = 16; o; o >>= 1) s += __shfl_xor_sync(0xffffffffu, s, o);
        const float inv = 1.f / s;
        __nv_bfloat16* q = gOut + (size_t)(m0 + r) * CC;
        #pragma unroll
        for (int j = 0; j < 8; ++j)
            q[lane + 32 * j] = __float2bfloat16_rn(e[j] * inv);
    }
}

// ---------------------------------------------------------------------------
// Kernel 4: projection GEMM + residual, mma.sync bf16.
//   Per batch: D[4096, 256] = [x1t | x2t] (K=512) @ [ab1 | ab2]^T
//   out[b, n*256+c] = D[n,c] + x1[o] + x2[o]
//   CTA tile 128x128, BK=64, 3-stage cp.async pipeline, ONE sync per chunk.
// ---------------------------------------------------------------------------
#define PJ_BUF  32768
#define PJ_SMEM (3 * PJ_BUF)            // 98304; 2 CTAs/SM = 192KB <= 228KB

__global__ void __launch_bounds__(256, 2) proj_mma(const float* __restrict__ x1,
                                                   const float* __restrict__ x2,
                                                   float* __restrict__ out) {
    extern __shared__ char smem[];
    const uint32_t sb = smem_to_u32(smem);
    const int tid = threadIdx.x, lane = tid & 31, wid = tid >> 5;
    const int b  = blockIdx.z;
    const int n0 = blockIdx.y * 128;              // spatial (M)
    const int c0 = blockIdx.x * 128;              // channel (N)

    const uint4* gA1 = (const uint4*)g_x1t + ((size_t)b * NN + n0) * (CC / 8);
    const uint4* gA2 = (const uint4*)g_x2t + ((size_t)b * NN + n0) * (CC / 8);
    const uint4* gB1 = (const uint4*)g_ab1 + ((size_t)(b * CC + c0)) * (CC / 8);
    const uint4* gB2 = (const uint4*)g_ab2 + ((size_t)(b * CC + c0)) * (CC / 8);

    const int mW = (wid >> 2) * 64;
    const int nW = (wid & 3) * 32;
    const int lrow = lane & 15;
    const int lhi  = lane >> 4;

    float acc[4][4][4] = {};

    auto prefetch = [&](int ch, int buf) {
        const uint4* pa = (ch < 4) ? gA1 : gA2;
        const uint4* pb = (ch < 4) ? gB1 : gB2;
        const int kc = (ch & 3) * 8;              // uint4 offset within 256-half
        const uint32_t aB = sb + buf * PJ_BUF;
        const uint32_t bB = aB + 16384;
        #pragma unroll
        for (int i = 0; i < 4; ++i) {
            const int lin = i * 256 + tid;
            const int r = lin >> 3, c = lin & 7;
            const uint32_t off = r * 128 + ((c ^ (r & 7)) << 4);
            cp16(aB + off, pa + (size_t)r * (CC / 8) + kc + c);
            cp16(bB + off, pb + (size_t)r * (CC / 8) + kc + c);
        }
        cp_commit();
    };

    prefetch(0, 0);
    prefetch(1, 1);
    #pragma unroll 1
    for (int ch = 0; ch < 8; ++ch) {
        if (ch + 1 < 8) cp_wait<1>();             // oldest (ch) complete
        else            cp_wait<0>();
        __syncthreads();                          // all warps done with ch-1
        if (ch + 2 < 8) prefetch(ch + 2, (ch + 2) % 3);

        const uint32_t aB = sb + (ch % 3) * PJ_BUF;
        const uint32_t bB = aB + 16384;
        #pragma unroll
        for (int ks = 0; ks < 4; ++ks) {
            uint32_t afr[4][4], bfr[2][4];
            #pragma unroll
            for (int mi = 0; mi < 4; ++mi) {
                const int r = mW + 16 * mi + lrow;
                ldsm4(afr[mi], aB + r * 128 + ((((ks << 1) | lhi) ^ (r & 7)) << 4));
            }
            #pragma unroll
            for (int nj = 0; nj < 2; ++nj) {
                const int r = nW + 16 * nj + lrow;
                ldsm4(bfr[nj], bB + r * 128 + ((((ks << 1) | lhi) ^ (r & 7)) << 4));
            }
            #pragma unroll
            for (int mi = 0; mi < 4; ++mi)
                #pragma unroll
                for (int ni = 0; ni < 4; ++ni)
                    mma16816(acc[mi][ni], afr[mi],
                             bfr[ni >> 1][ni & 1], bfr[ni >> 1][(ni & 1) + 2]);
        }
    }

    // Epilogue: out[o] = acc + x1[o] + x2[o],  o = b*CC*NN + n*CC + c
    const size_t ob = (size_t)b * CC * NN;
    #pragma unroll
    for (int mi = 0; mi < 4; ++mi) {
        const int n = n0 + mW + 16 * mi + (lane >> 2);
        #pragma unroll
        for (int ni = 0; ni < 4; ++ni) {
            const int c = c0 + nW + 8 * ni + 2 * (lane & 3);
            {
                const size_t o = ob + (size_t)n * CC + c;
                float2 r1 = *(const float2*)(x1 + o);
                float2 r2 = *(const float2*)(x2 + o);
                *(float2*)(out + o) = make_float2(acc[mi][ni][0] + r1.x + r2.x,
                                                  acc[mi][ni][1] + r1.y + r2.y);
            }
            {
                const size_t o = ob + (size_t)(n + 8) * CC + c;
                float2 r1 = *(const float2*)(x1 + o);
                float2 r2 = *(const float2*)(x2 + o);
                *(float2*)(out + o) = make_float2(acc[mi][ni][2] + r1.x + r2.x,
                                                  acc[mi][ni][3] + r1.y + r2.y);
            }
        }
    }
}

// ---------------------------------------------------------------------------
extern "C" void kernel_launch(void* const* d_in, const int* in_sizes, int n_in,
                              void* d_out, int out_size) {
    const float* x1 = (const float*)d_in[0];
    const float* x2 = (const float*)d_in[1];
    float* out = (float*)d_out;

    cudaFuncSetAttribute(score_mma, cudaFuncAttributeMaxDynamicSharedMemorySize, SC_SMEM);
    cudaFuncSetAttribute(proj_mma,  cudaFuncAttributeMaxDynamicSharedMemorySize, PJ_SMEM);

    fuse_k     <<<BB * CC, 256>>>(x1, x2);
    transpose_k<<<dim3(NN / 32, CC / 32, BB), dim3(32, 8)>>>();
    score_mma  <<<dim3(8, BB), 256, SC_SMEM>>>();
    proj_mma   <<<dim3(2, 32, BB), 256, PJ_SMEM>>>(x1, x2, out);
}

// round 17
// speedup vs baseline: 1.0124x; 1.0023x over previous
#include <cuda_runtime.h>
#include <cuda_bf16.h>
#include <cstdint>
#include <math.h>

#define BB 16
#define CC 256
#define NN 4096

// ---------------------------------------------------------------------------
// Device-global scratch (allocation-free per harness rules)
// ---------------------------------------------------------------------------
static __device__ __nv_bfloat16 g_s  [(size_t)BB * CC * NN];  // normalized sum
static __device__ __nv_bfloat16 g_x1b[(size_t)BB * CC * NN];  // bf16(x1) raw
static __device__ __nv_bfloat16 g_x2b[(size_t)BB * CC * NN];  // bf16(x2) raw
static __device__ __nv_bfloat16 g_x1t[(size_t)BB * CC * NN];  // bf16(x1) [b,n,d]
static __device__ __nv_bfloat16 g_x2t[(size_t)BB * CC * NN];
static __device__ float g_inv1[BB * CC];
static __device__ float g_inv2[BB * CC];
static __device__ __nv_bfloat16 g_ab1[(size_t)BB * CC * CC];  // softmaxed, bf16
static __device__ __nv_bfloat16 g_ab2[(size_t)BB * CC * CC];

// ---------------------------------------------------------------------------
// PTX helpers (base PTX only: cp.async / ldmatrix / mma.sync)
// ---------------------------------------------------------------------------
__device__ __forceinline__ uint32_t smem_to_u32(const void* p) {
    uint32_t a;
    asm("{ .reg .u64 t; cvta.to.shared.u64 t, %1; cvt.u32.u64 %0, t; }"
        : "=r"(a) : "l"(p));
    return a;
}

__device__ __forceinline__ void cp16(uint32_t dst, const void* src) {
    asm volatile("cp.async.cg.shared.global [%0], [%1], 16;\n"
                 :: "r"(dst), "l"(src));
}
__device__ __forceinline__ void cp_commit() {
    asm volatile("cp.async.commit_group;" ::: "memory");
}
template <int N>
__device__ __forceinline__ void cp_wait() {
    asm volatile("cp.async.wait_group %0;" :: "n"(N) : "memory");
}

__device__ __forceinline__ void ldsm4(uint32_t* r, uint32_t addr) {
    asm volatile("ldmatrix.sync.aligned.m8n8.x4.shared.b16 {%0,%1,%2,%3}, [%4];"
                 : "=r"(r[0]), "=r"(r[1]), "=r"(r[2]), "=r"(r[3])
                 : "r"(addr));
}

__device__ __forceinline__ void mma16816(float* c, const uint32_t* a,
                                         uint32_t b0, uint32_t b1) {
    asm volatile(
        "mma.sync.aligned.m16n8k16.row.col.f32.bf16.bf16.f32 "
        "{%0,%1,%2,%3}, {%4,%5,%6,%7}, {%8,%9}, {%0,%1,%2,%3};"
        : "+f"(c[0]), "+f"(c[1]), "+f"(c[2]), "+f"(c[3])
        : "r"(a[0]), "r"(a[1]), "r"(a[2]), "r"(a[3]), "r"(b0), "r"(b1));
}

__device__ __forceinline__ uint32_t pack2bf(float x, float y) {
    __nv_bfloat162 h = __floats2bfloat162_rn(x, y);
    return *reinterpret_cast<uint32_t*>(&h);
}
__device__ __forceinline__ uint2 pack4bf(float a, float b, float c, float d) {
    return make_uint2(pack2bf(a, b), pack2bf(c, d));
}

// ---------------------------------------------------------------------------
// Kernel 1: fused norm + bf16 conversion.  One block per (b,c) row.
//   g_s = bf16(x1*inv1 + x2*inv2); g_x1b/g_x2b = bf16 raw copies; invs saved.
// ---------------------------------------------------------------------------
__global__ void __launch_bounds__(256) fuse_k(const float* __restrict__ x1,
                                              const float* __restrict__ x2) {
    const int row = blockIdx.x;
    const size_t base4 = (size_t)row * (NN / 4);
    const float4* p1 = ((const float4*)x1) + base4;
    const float4* p2 = ((const float4*)x2) + base4;

    float4 a[4], c[4];
    float s1 = 0.f, s2 = 0.f;
    #pragma unroll
    for (int i = 0; i < 4; ++i) {
        a[i] = p1[threadIdx.x + i * 256];
        c[i] = p2[threadIdx.x + i * 256];
        s1 += a[i].x * a[i].x + a[i].y * a[i].y + a[i].z * a[i].z + a[i].w * a[i].w;
        s2 += c[i].x * c[i].x + c[i].y * c[i].y + c[i].z * c[i].z + c[i].w * c[i].w;
    }
    __shared__ float sh1[8], sh2[8];
    __shared__ float b_i1, b_i2;
    const int lane = threadIdx.x & 31, w = threadIdx.x >> 5;
    #pragma unroll
    for (int o = 16; o; o >>= 1) {
        s1 += __shfl_xor_sync(0xffffffffu, s1, o);
        s2 += __shfl_xor_sync(0xffffffffu, s2, o);
    }
    if (lane == 0) { sh1[w] = s1; sh2[w] = s2; }
    __syncthreads();
    if (threadIdx.x < 32) {
        s1 = (lane < 8) ? sh1[lane] : 0.f;
        s2 = (lane < 8) ? sh2[lane] : 0.f;
        #pragma unroll
        for (int o = 4; o; o >>= 1) {
            s1 += __shfl_xor_sync(0xffffffffu, s1, o);
            s2 += __shfl_xor_sync(0xffffffffu, s2, o);
        }
        if (lane == 0) {
            b_i1 = 1.f / fmaxf(sqrtf(s1), 1e-12f);
            b_i2 = 1.f / fmaxf(sqrtf(s2), 1e-12f);
            g_inv1[row] = b_i1;
            g_inv2[row] = b_i2;
        }
    }
    __syncthreads();
    const float i1 = b_i1, i2 = b_i2;

    uint2* os  = reinterpret_cast<uint2*>(g_s)   + base4;
    uint2* o1b = reinterpret_cast<uint2*>(g_x1b) + base4;
    uint2* o2b = reinterpret_cast<uint2*>(g_x2b) + base4;
    #pragma unroll
    for (int i = 0; i < 4; ++i) {
        const int idx = threadIdx.x + i * 256;
        o1b[idx] = pack4bf(a[i].x, a[i].y, a[i].z, a[i].w);
        o2b[idx] = pack4bf(c[i].x, c[i].y, c[i].z, c[i].w);
        os [idx] = pack4bf(a[i].x * i1 + c[i].x * i2, a[i].y * i1 + c[i].y * i2,
                           a[i].z * i1 + c[i].z * i2, a[i].w * i1 + c[i].w * i2);
    }
}

// ---------------------------------------------------------------------------
// Kernel 2: transpose bf16 -> bf16 [b, n, d].  Reads the already-converted
// g_x1b/g_x2b (half the traffic of reading fp32 x1/x2; bit-identical output).
// uint16 smem [32][34]: column reads word-stride 17 (odd) -> conflict-free.
// ---------------------------------------------------------------------------
__global__ void __launch_bounds__(256) transpose_k() {
    __shared__ uint16_t t1[32][34], t2[32][34];
    const int b  = blockIdx.z;
    const int c0 = blockIdx.y * 32;
    const int n0 = blockIdx.x * 32;
    const int tx = threadIdx.x, ty = threadIdx.y;   // 32 x 8

    const uint16_t* s1 = (const uint16_t*)g_x1b;
    const uint16_t* s2 = (const uint16_t*)g_x2b;
    #pragma unroll
    for (int i = 0; i < 4; ++i) {
        const int r = ty + i * 8;
        const size_t idx = ((size_t)(b * CC + c0 + r)) * NN + n0 + tx;
        t1[r][tx] = s1[idx];
        t2[r][tx] = s2[idx];
    }
    __syncthreads();
    uint16_t* d1 = (uint16_t*)g_x1t;
    uint16_t* d2 = (uint16_t*)g_x2t;
    #pragma unroll
    for (int i = 0; i < 4; ++i) {
        const int r = ty + i * 8;
        const size_t o = ((size_t)b * NN + n0 + r) * CC + c0 + tx;
        d1[o] = t1[tx][r];
        d2[o] = t2[tx][r];
    }
}

// ---------------------------------------------------------------------------
// Kernel 3: score GEMM + fused softmax, mma.sync bf16 (round-7 proven shape).
//   scores[64, 256] = s[m0:m0+64, :] @ xRAW[0:256, :]^T, column-scale by
//   inv[d], row-softmax, bf16 out.  Stash aliases dead tile buffers.
// ---------------------------------------------------------------------------
#define SC_BUF    40960                 // A (64x64x2=8KB) + B (256x64x2=32KB)
#define SC_SP     268                   // stash row stride (floats)
#define SC_SMEM   (2 * SC_BUF)          // 81920 >= 64*SC_SP*4 = 68608

__global__ void __launch_bounds__(256, 2) score_mma() {
    extern __shared__ char smem[];
    const uint32_t sb = smem_to_u32(smem);
    const int tid = threadIdx.x, lane = tid & 31, wid = tid >> 5;
    const int b   = blockIdx.y;
    const int sel = blockIdx.x >> 2;
    const int m0  = (blockIdx.x & 3) * 64;

    const __nv_bfloat16* bsrc = sel ? g_x2b : g_x1b;
    const float* ginv = (sel ? g_inv2 : g_inv1) + b * CC;
    __nv_bfloat16* gOut = (sel ? g_ab2 : g_ab1) + (size_t)b * CC * CC;
    const uint4* gA = (const uint4*)g_s  + (size_t)(b * CC + m0) * (NN / 8);
    const uint4* gB = (const uint4*)bsrc + (size_t)(b * CC) * (NN / 8);

    const int mW = (wid >> 2) * 32;               // warp m offset (0/32)
    const int nW = (wid & 3) * 64;                // warp d offset (0..192)
    const int lrow = lane & 15;
    const int lhi  = lane >> 4;

    float acc[2][8][4] = {};

    auto prefetch = [&](int ch, int buf) {
        const uint32_t aB = sb + buf * SC_BUF;
        const uint32_t bB = aB + 8192;
        #pragma unroll
        for (int i = 0; i < 2; ++i) {
            const int lin = i * 256 + tid;
            const int r = lin >> 3, c = lin & 7;
            cp16(aB + r * 128 + ((c ^ (r & 7)) << 4),
                 gA + (size_t)r * (NN / 8) + ch * 8 + c);
        }
        #pragma unroll
        for (int i = 0; i < 8; ++i) {
            const int lin = i * 256 + tid;
            const int r = lin >> 3, c = lin & 7;
            cp16(bB + r * 128 + ((c ^ (r & 7)) << 4),
                 gB + (size_t)r * (NN / 8) + ch * 8 + c);
        }
        cp_commit();
    };

    prefetch(0, 0);
    for (int ch = 0; ch < NN / 64; ++ch) {
        const int buf = ch & 1;
        if (ch + 1 < NN / 64) { prefetch(ch + 1, buf ^ 1); cp_wait<1>(); }
        else                  { cp_wait<0>(); }
        __syncthreads();

        const uint32_t aB = sb + buf * SC_BUF;
        const uint32_t bB = aB + 8192;
        #pragma unroll
        for (int ks = 0; ks < 4; ++ks) {
            uint32_t afr[2][4], bfr[4][4];
            #pragma unroll
            for (int mi = 0; mi < 2; ++mi) {
                const int r = mW + 16 * mi + lrow;
                ldsm4(afr[mi], aB + r * 128 + ((((ks << 1) | lhi) ^ (r & 7)) << 4));
            }
            #pragma unroll
            for (int nj = 0; nj < 4; ++nj) {
                const int r = nW + 16 * nj + lrow;
                ldsm4(bfr[nj], bB + r * 128 + ((((ks << 1) | lhi) ^ (r & 7)) << 4));
            }
            #pragma unroll
            for (int mi = 0; mi < 2; ++mi)
                #pragma unroll
                for (int ni = 0; ni < 8; ++ni)
                    mma16816(acc[mi][ni], afr[mi],
                             bfr[ni >> 1][ni & 1], bfr[ni >> 1][(ni & 1) + 2]);
        }
        __syncthreads();
    }

    // Stash aliases the (now dead) tile buffers; last loop sync protects it.
    float* stash = (float*)smem;
    float invv[8];
    #pragma unroll
    for (int j = 0; j < 8; ++j) invv[j] = ginv[lane + 32 * j];

    #pragma unroll
    for (int mi = 0; mi < 2; ++mi) {
        const int r = mW + 16 * mi + (lane >> 2);
        #pragma unroll
        for (int ni = 0; ni < 8; ++ni) {
            const int d = nW + 8 * ni + 2 * (lane & 3);
            *(float2*)&stash[(size_t)r * SC_SP + d] =
                make_float2(acc[mi][ni][0], acc[mi][ni][1]);
            *(float2*)&stash[(size_t)(r + 8) * SC_SP + d] =
                make_float2(acc[mi][ni][2], acc[mi][ni][3]);
        }
    }
    __syncthreads();

    #pragma unroll
    for (int i = 0; i < 8; ++i) {
        const int r = wid * 8 + i;
        const float* srow = stash + (size_t)r * SC_SP;
        float v[8];
        #pragma unroll
        for (int j = 0; j < 8; ++j) v[j] = srow[lane + 32 * j] * invv[j];
        float m = v[0];
        #pragma unroll
        for (int j = 1; j < 8; ++j) m = fmaxf(m, v[j]);
        #pragma unroll
        for (int o = 16; o; o >>= 1) m = fmaxf(m, __shfl_xor_sync(0xffffffffu, m, o));
        float e[8], s = 0.f;
        #pragma unroll
        for (int j = 0; j < 8; ++j) { e[j] = __expf(v[j] - m); s += e[j]; }
        #pragma unroll
        for (int o = 16; o; o >>= 1) s += __shfl_xor_sync(0xffffffffu, s, o);
        const float inv = 1.f / s;
        __nv_bfloat16* q = gOut + (size_t)(m0 + r) * CC;
        #pragma unroll
        for (int j = 0; j < 8; ++j)
            q[lane + 32 * j] = __float2bfloat16_rn(e[j] * inv);
    }
}

// ---------------------------------------------------------------------------
// Kernel 4: projection GEMM + residual, mma.sync bf16.
//   Per batch: D[4096, 256] = [x1t | x2t] (K=512) @ [ab1 | ab2]^T
//   out[b, n*256+c] = D[n,c] + x1[o] + x2[o]
//   CTA tile 128x128, BK=64, 3-stage cp.async pipeline, ONE sync per chunk.
// ---------------------------------------------------------------------------
#define PJ_BUF  32768
#define PJ_SMEM (3 * PJ_BUF)            // 98304; 2 CTAs/SM = 192KB <= 228KB

__global__ void __launch_bounds__(256, 2) proj_mma(const float* __restrict__ x1,
                                                   const float* __restrict__ x2,
                                                   float* __restrict__ out) {
    extern __shared__ char smem[];
    const uint32_t sb = smem_to_u32(smem);
    const int tid = threadIdx.x, lane = tid & 31, wid = tid >> 5;
    const int b  = blockIdx.z;
    const int n0 = blockIdx.y * 128;              // spatial (M)
    const int c0 = blockIdx.x * 128;              // channel (N)

    const uint4* gA1 = (const uint4*)g_x1t + ((size_t)b * NN + n0) * (CC / 8);
    const uint4* gA2 = (const uint4*)g_x2t + ((size_t)b * NN + n0) * (CC / 8);
    const uint4* gB1 = (const uint4*)g_ab1 + ((size_t)(b * CC + c0)) * (CC / 8);
    const uint4* gB2 = (const uint4*)g_ab2 + ((size_t)(b * CC + c0)) * (CC / 8);

    const int mW = (wid >> 2) * 64;
    const int nW = (wid & 3) * 32;
    const int lrow = lane & 15;
    const int lhi  = lane >> 4;

    float acc[4][4][4] = {};

    auto prefetch = [&](int ch, int buf) {
        const uint4* pa = (ch < 4) ? gA1 : gA2;
        const uint4* pb = (ch < 4) ? gB1 : gB2;
        const int kc = (ch & 3) * 8;              // uint4 offset within 256-half
        const uint32_t aB = sb + buf * PJ_BUF;
        const uint32_t bB = aB + 16384;
        #pragma unroll
        for (int i = 0; i < 4; ++i) {
            const int lin = i * 256 + tid;
            const int r = lin >> 3, c = lin & 7;
            const uint32_t off = r * 128 + ((c ^ (r & 7)) << 4);
            cp16(aB + off, pa + (size_t)r * (CC / 8) + kc + c);
            cp16(bB + off, pb + (size_t)r * (CC / 8) + kc + c);
        }
        cp_commit();
    };

    prefetch(0, 0);
    prefetch(1, 1);
    #pragma unroll 1
    for (int ch = 0; ch < 8; ++ch) {
        if (ch + 1 < 8) cp_wait<1>();             // oldest (ch) complete
        else            cp_wait<0>();
        __syncthreads();                          // all warps done with ch-1
        if (ch + 2 < 8) prefetch(ch + 2, (ch + 2) % 3);

        const uint32_t aB = sb + (ch % 3) * PJ_BUF;
        const uint32_t bB = aB + 16384;
        #pragma unroll
        for (int ks = 0; ks < 4; ++ks) {
            uint32_t afr[4][4], bfr[2][4];
            #pragma unroll
            for (int mi = 0; mi < 4; ++mi) {
                const int r = mW + 16 * mi + lrow;
                ldsm4(afr[mi], aB + r * 128 + ((((ks << 1) | lhi) ^ (r & 7)) << 4));
            }
            #pragma unroll
            for (int nj = 0; nj < 2; ++nj) {
                const int r = nW + 16 * nj + lrow;
                ldsm4(bfr[nj], bB + r * 128 + ((((ks << 1) | lhi) ^ (r & 7)) << 4));
            }
            #pragma unroll
            for (int mi = 0; mi < 4; ++mi)
                #pragma unroll
                for (int ni = 0; ni < 4; ++ni)
                    mma16816(acc[mi][ni], afr[mi],
                             bfr[ni >> 1][ni & 1], bfr[ni >> 1][(ni & 1) + 2]);
        }
    }

    // Epilogue: out[o] = acc + x1[o] + x2[o],  o = b*CC*NN + n*CC + c
    const size_t ob = (size_t)b * CC * NN;
    #pragma unroll
    for (int mi = 0; mi < 4; ++mi) {
        const int n = n0 + mW + 16 * mi + (lane >> 2);
        #pragma unroll
        for (int ni = 0; ni < 4; ++ni) {
            const int c = c0 + nW + 8 * ni + 2 * (lane & 3);
            {
                const size_t o = ob + (size_t)n * CC + c;
                float2 r1 = *(const float2*)(x1 + o);
                float2 r2 = *(const float2*)(x2 + o);
                *(float2*)(out + o) = make_float2(acc[mi][ni][0] + r1.x + r2.x,
                                                  acc[mi][ni][1] + r1.y + r2.y);
            }
            {
                const size_t o = ob + (size_t)(n + 8) * CC + c;
                float2 r1 = *(const float2*)(x1 + o);
                float2 r2 = *(const float2*)(x2 + o);
                *(float2*)(out + o) = make_float2(acc[mi][ni][2] + r1.x + r2.x,
                                                  acc[mi][ni][3] + r1.y + r2.y);
            }
        }
    }
}

// ---------------------------------------------------------------------------
extern "C" void kernel_launch(void* const* d_in, const int* in_sizes, int n_in,
                              void* d_out, int out_size) {
    const float* x1 = (const float*)d_in[0];
    const float* x2 = (const float*)d_in[1];
    float* out = (float*)d_out;

    cudaFuncSetAttribute(score_mma, cudaFuncAttributeMaxDynamicSharedMemorySize, SC_SMEM);
    cudaFuncSetAttribute(proj_mma,  cudaFuncAttributeMaxDynamicSharedMemorySize, PJ_SMEM);

    fuse_k     <<<BB * CC, 256>>>(x1, x2);
    transpose_k<<<dim3(NN / 32, CC / 32, BB), dim3(32, 8)>>>();
    score_mma  <<<dim3(8, BB), 256, SC_SMEM>>>();
    proj_mma   <<<dim3(2, 32, BB), 256, PJ_SMEM>>>(x1, x2, out);
}